// round 2
// baseline (speedup 1.0000x reference)
#include <cuda_runtime.h>
#include <math.h>

#define T_TOKENS 2048
#define HID      1024
#define INTER    2048
#define NEXP     8
#define NPAIRS   (T_TOKENS * 2)   // 4096 token-expert pairs total

// ---------------- scratch (static __device__ — no runtime allocation) -------
__device__ int   g_counts[NEXP];                 // rows per expert
__device__ int   g_pairs[NEXP * NPAIRS];         // per-expert list of (token*2+slot)
__device__ float g_w[T_TOKENS * 2];              // routing weights per (token, slot)
__device__ float g_inter[(size_t)NPAIRS * INTER];// 32 MB  silu(h0)*h1
__device__ float g_y[(size_t)NPAIRS * HID];      // 16 MB  expert outputs per pair

// ---------------- kernel 0: zero the atomic counters ------------------------
__global__ void zero_counts_kernel() {
    if (threadIdx.x < NEXP) g_counts[threadIdx.x] = 0;
}

// ---------------- kernel 1: routing (top-2 of 8 + softmax + scatter) --------
__global__ void route_kernel(const float* __restrict__ logits) {
    int t = blockIdx.x * blockDim.x + threadIdx.x;
    if (t >= T_TOKENS) return;

    float l[NEXP];
#pragma unroll
    for (int e = 0; e < NEXP; e++) l[e] = logits[t * NEXP + e];

    // argmax (first index on ties, matching jax top_k)
    int i0 = 0; float v0 = l[0];
#pragma unroll
    for (int e = 1; e < NEXP; e++) { if (l[e] > v0) { v0 = l[e]; i0 = e; } }
    // second max excluding i0
    int i1 = -1; float v1 = -__FLT_MAX__;
#pragma unroll
    for (int e = 0; e < NEXP; e++) {
        if (e == i0) continue;
        if (l[e] > v1) { v1 = l[e]; i1 = e; }
    }

    // softmax over [v0, v1] (v0 >= v1)
    float e1 = expf(v1 - v0);
    float s  = 1.0f + e1;
    g_w[t * 2 + 0] = 1.0f / s;
    g_w[t * 2 + 1] = e1 / s;

    int p0 = atomicAdd(&g_counts[i0], 1);
    g_pairs[i0 * NPAIRS + p0] = t * 2 + 0;
    int p1 = atomicAdd(&g_counts[i1], 1);
    g_pairs[i1 * NPAIRS + p1] = t * 2 + 1;
}

// ---------------- kernel 2: GEMM1 — x @ wi_0[e] and x @ wi_1[e], fused SwiGLU
// Tile: 128(M) x 64(N per matrix) x 8(K), 256 threads, each thread 8x4 per matrix.
__global__ __launch_bounds__(256) void gemm1_kernel(
    const float* __restrict__ x,
    const float* __restrict__ wi0,
    const float* __restrict__ wi1)
{
    const int e   = blockIdx.z;
    const int cnt = g_counts[e];
    const int m0  = blockIdx.y * 128;
    if (m0 >= cnt) return;
    const int n0  = blockIdx.x * 64;

    const float* B0 = wi0 + (size_t)e * HID * INTER;
    const float* B1 = wi1 + (size_t)e * HID * INTER;

    __shared__ float As [8][128];
    __shared__ float B0s[8][64];
    __shared__ float B1s[8][64];

    const int tid = threadIdx.x;

    // A gather: one float4 per thread per k-step
    const int am = tid >> 1;           // 0..127 (tile row)
    const int ac = (tid & 1) * 4;      // 0 or 4 (k offset)
    const float* arow = nullptr;
    {
        int mg = m0 + am;
        if (mg < cnt) {
            int entry = g_pairs[e * NPAIRS + mg];
            arow = x + (size_t)(entry >> 1) * HID;   // token = entry/2
        }
    }

    // B load mapping: one float2 per matrix per thread per k-step
    const int bk = tid >> 5;           // 0..7
    const int bn = (tid & 31) * 2;     // 0..62

    const int ty = tid >> 4;           // 0..15  rows ty*8 .. ty*8+7
    const int tx = tid & 15;           // 0..15  cols tx*4 .. tx*4+3

    float acc0[8][4], acc1[8][4];
#pragma unroll
    for (int i = 0; i < 8; i++)
#pragma unroll
        for (int j = 0; j < 4; j++) { acc0[i][j] = 0.f; acc1[i][j] = 0.f; }

    for (int k0 = 0; k0 < HID; k0 += 8) {
        float4 av = make_float4(0.f, 0.f, 0.f, 0.f);
        if (arow) av = *(const float4*)(arow + k0 + ac);
        float2 b0v = *(const float2*)(B0 + (size_t)(k0 + bk) * INTER + n0 + bn);
        float2 b1v = *(const float2*)(B1 + (size_t)(k0 + bk) * INTER + n0 + bn);

        __syncthreads();
        As[ac + 0][am] = av.x;
        As[ac + 1][am] = av.y;
        As[ac + 2][am] = av.z;
        As[ac + 3][am] = av.w;
        B0s[bk][bn] = b0v.x; B0s[bk][bn + 1] = b0v.y;
        B1s[bk][bn] = b1v.x; B1s[bk][bn + 1] = b1v.y;
        __syncthreads();

#pragma unroll
        for (int kk = 0; kk < 8; kk++) {
            float a[8], b0[4], b1[4];
#pragma unroll
            for (int i = 0; i < 8; i++) a[i] = As[kk][ty * 8 + i];
#pragma unroll
            for (int j = 0; j < 4; j++) { b0[j] = B0s[kk][tx * 4 + j]; b1[j] = B1s[kk][tx * 4 + j]; }
#pragma unroll
            for (int i = 0; i < 8; i++)
#pragma unroll
                for (int j = 0; j < 4; j++) {
                    acc0[i][j] = fmaf(a[i], b0[j], acc0[i][j]);
                    acc1[i][j] = fmaf(a[i], b1[j], acc1[i][j]);
                }
        }
    }

    // epilogue: inter = silu(h0) * h1, scattered to the pair's row
#pragma unroll
    for (int i = 0; i < 8; i++) {
        int m = m0 + ty * 8 + i;
        if (m >= cnt) continue;
        int entry = g_pairs[e * NPAIRS + m];
        float* orow = g_inter + (size_t)entry * INTER + n0 + tx * 4;
#pragma unroll
        for (int j = 0; j < 4; j++) {
            float h0 = acc0[i][j];
            float h1 = acc1[i][j];
            float sil = h0 / (1.0f + expf(-h0));
            orow[j] = sil * h1;
        }
    }
}

// ---------------- kernel 3: GEMM2 — inter @ wo[e] ---------------------------
// Tile: 128(M) x 128(N) x 8(K), 256 threads, 8x8 per thread.
__global__ __launch_bounds__(256) void gemm2_kernel(const float* __restrict__ wo)
{
    const int e   = blockIdx.z;
    const int cnt = g_counts[e];
    const int m0  = blockIdx.y * 128;
    if (m0 >= cnt) return;
    const int n0  = blockIdx.x * 128;

    const float* B = wo + (size_t)e * INTER * HID;

    __shared__ float As[8][128];
    __shared__ float Bs[8][128];

    const int tid = threadIdx.x;

    const int am = tid >> 1;
    const int ac = (tid & 1) * 4;
    const float* arow = nullptr;
    {
        int mg = m0 + am;
        if (mg < cnt) {
            int entry = g_pairs[e * NPAIRS + mg];
            arow = g_inter + (size_t)entry * INTER;
        }
    }

    const int bk = tid >> 5;           // 0..7
    const int bn = (tid & 31) * 4;     // 0..124

    const int ty = tid >> 4;
    const int tx = tid & 15;

    float acc[8][8];
#pragma unroll
    for (int i = 0; i < 8; i++)
#pragma unroll
        for (int j = 0; j < 8; j++) acc[i][j] = 0.f;

    for (int k0 = 0; k0 < INTER; k0 += 8) {
        float4 av = make_float4(0.f, 0.f, 0.f, 0.f);
        if (arow) av = *(const float4*)(arow + k0 + ac);
        float4 bv = *(const float4*)(B + (size_t)(k0 + bk) * HID + n0 + bn);

        __syncthreads();
        As[ac + 0][am] = av.x;
        As[ac + 1][am] = av.y;
        As[ac + 2][am] = av.z;
        As[ac + 3][am] = av.w;
        *(float4*)&Bs[bk][bn] = bv;
        __syncthreads();

#pragma unroll
        for (int kk = 0; kk < 8; kk++) {
            float a[8], b[8];
#pragma unroll
            for (int i = 0; i < 8; i++) a[i] = As[kk][ty * 8 + i];
#pragma unroll
            for (int j = 0; j < 8; j++) b[j] = Bs[kk][tx * 8 + j];
#pragma unroll
            for (int i = 0; i < 8; i++)
#pragma unroll
                for (int j = 0; j < 8; j++)
                    acc[i][j] = fmaf(a[i], b[j], acc[i][j]);
        }
    }

#pragma unroll
    for (int i = 0; i < 8; i++) {
        int m = m0 + ty * 8 + i;
        if (m >= cnt) continue;
        int entry = g_pairs[e * NPAIRS + m];
        float* yrow = g_y + (size_t)entry * HID + n0 + tx * 8;
#pragma unroll
        for (int j = 0; j < 8; j += 4)
            *(float4*)(yrow + j) = make_float4(acc[i][j], acc[i][j+1], acc[i][j+2], acc[i][j+3]);
    }
}

// ---------------- kernel 4: weighted combine --------------------------------
__global__ void combine_kernel(float* __restrict__ out)
{
    int t = blockIdx.x;
    float w0 = g_w[2 * t + 0];
    float w1 = g_w[2 * t + 1];
    const float4* y0 = (const float4*)(g_y + (size_t)(2 * t + 0) * HID);
    const float4* y1 = (const float4*)(g_y + (size_t)(2 * t + 1) * HID);
    float4* o = (float4*)(out + (size_t)t * HID);
    for (int h = threadIdx.x; h < HID / 4; h += blockDim.x) {
        float4 a = y0[h], b = y1[h];
        o[h] = make_float4(w0 * a.x + w1 * b.x,
                           w0 * a.y + w1 * b.y,
                           w0 * a.z + w1 * b.z,
                           w0 * a.w + w1 * b.w);
    }
}

// ---------------- launch -----------------------------------------------------
extern "C" void kernel_launch(void* const* d_in, const int* in_sizes, int n_in,
                              void* d_out, int out_size)
{
    const float* x      = (const float*)d_in[0];  // [2048, 1024]
    const float* logits = (const float*)d_in[1];  // [2048, 8]
    const float* wi0    = (const float*)d_in[2];  // [8, 1024, 2048]
    const float* wi1    = (const float*)d_in[3];  // [8, 1024, 2048]
    const float* wo     = (const float*)d_in[4];  // [8, 2048, 1024]
    float* out          = (float*)d_out;          // [2048, 1024]

    zero_counts_kernel<<<1, 32>>>();
    route_kernel<<<T_TOKENS / 256, 256>>>(logits);

    dim3 g1(INTER / 64, NPAIRS / 128, NEXP);   // (32, 32, 8), empty m-tiles early-exit
    gemm1_kernel<<<g1, 256>>>(x, wi0, wi1);

    dim3 g2(HID / 128, NPAIRS / 128, NEXP);    // (8, 32, 8)
    gemm2_kernel<<<g2, 256>>>(wo);

    combine_kernel<<<T_TOKENS, 256>>>(out);
}

// round 4
// speedup vs baseline: 2.0744x; 2.0744x over previous
#include <cuda_runtime.h>
#include <math.h>
#include <stdint.h>

#define T_TOKENS 2048
#define HID      1024
#define INTER    2048
#define NEXP     8
#define NPAIRS   (T_TOKENS * 2)
#define AS       36            // padded smem k-stride (floats)

// ---------------- scratch -----------------------------------------------------
__device__ int   g_counts[NEXP];
__device__ int   g_pairs[NEXP * NPAIRS];
__device__ float g_w[NPAIRS];
__device__ float g_inter[(size_t)NPAIRS * INTER]; // 32 MB
__device__ float g_y[(size_t)NPAIRS * HID];       // 16 MB

// ---------------- helpers -------------------------------------------------------
__device__ __forceinline__ float tf(float f) {
    uint32_t r;
    asm("cvt.rna.tf32.f32 %0, %1;" : "=r"(r) : "f"(f));
    return __uint_as_float(r);
}

__device__ __forceinline__ void mma8(float* d, const uint32_t* a, const uint32_t* b) {
    asm volatile(
        "mma.sync.aligned.m16n8k8.row.col.f32.tf32.tf32.f32 "
        "{%0,%1,%2,%3}, {%4,%5,%6,%7}, {%8,%9}, {%0,%1,%2,%3};"
        : "+f"(d[0]), "+f"(d[1]), "+f"(d[2]), "+f"(d[3])
        : "r"(a[0]), "r"(a[1]), "r"(a[2]), "r"(a[3]), "r"(b[0]), "r"(b[1]));
}

// ---------------- routing --------------------------------------------------------
__global__ void zero_counts_kernel() {
    if (threadIdx.x < NEXP) g_counts[threadIdx.x] = 0;
}

__global__ void route_kernel(const float* __restrict__ logits) {
    int t = blockIdx.x * blockDim.x + threadIdx.x;
    if (t >= T_TOKENS) return;
    float l[NEXP];
#pragma unroll
    for (int e = 0; e < NEXP; e++) l[e] = logits[t * NEXP + e];
    int i0 = 0; float v0 = l[0];
#pragma unroll
    for (int e = 1; e < NEXP; e++) if (l[e] > v0) { v0 = l[e]; i0 = e; }
    int i1 = -1; float v1 = -__FLT_MAX__;
#pragma unroll
    for (int e = 0; e < NEXP; e++) {
        if (e == i0) continue;
        if (l[e] > v1) { v1 = l[e]; i1 = e; }
    }
    float e1 = expf(v1 - v0);
    float s  = 1.0f + e1;
    g_w[t * 2 + 0] = 1.0f / s;
    g_w[t * 2 + 1] = e1 / s;
    int p0 = atomicAdd(&g_counts[i0], 1);
    g_pairs[i0 * NPAIRS + p0] = t * 2 + 0;
    int p1 = atomicAdd(&g_counts[i1], 1);
    g_pairs[i1 * NPAIRS + p1] = t * 2 + 1;
}

// ---------------- GEMM1: x @ {wi0, wi1}[e] + fused SwiGLU ------------------------
// CTA tile 128M x 64N (per matrix), k-chunk 32, double buffered.
// 8 warps in 2(M) x 4(N); warp tile 64 x 16 per matrix; m16n8k8 tf32 mma.sync.
__global__ __launch_bounds__(256) void gemm1_mma(
    const float* __restrict__ x,
    const float* __restrict__ wi0,
    const float* __restrict__ wi1)
{
    const int e   = blockIdx.z;
    const int cnt = g_counts[e];
    const int m0  = blockIdx.y * 128;
    if (m0 >= cnt) return;
    const int n0  = blockIdx.x * 64;
    const float* B0g = wi0 + (size_t)e * HID * INTER;
    const float* B1g = wi1 + (size_t)e * HID * INTER;

    extern __shared__ float sm[];
    float* sA  = sm;                     // [2][128*AS]
    float* sB0 = sm + 2 * 128 * AS;      // [2][64*AS]
    float* sB1 = sB0 + 2 * 64 * AS;      // [2][64*AS]

    const int tid = threadIdx.x, lane = tid & 31, wid = tid >> 5;
    const int wm = wid >> 2, wn = wid & 3;
    const int gq = lane >> 2, tg = lane & 3;

    // A gather pointer (row constant per thread)
    const int ar = tid >> 1, acf = (tid & 1) * 16;
    const float* arow = nullptr;
    {
        int mg = m0 + ar;
        if (mg < cnt) arow = x + (size_t)(g_pairs[e * NPAIRS + mg] >> 1) * HID;
    }

    float4 aR[4];
    float  b0R[8], b1R[8];

    auto load_chunk = [&](int k0) {
#pragma unroll
        for (int q = 0; q < 4; q++)
            aR[q] = arow ? *(const float4*)(arow + k0 + acf + q * 4)
                         : make_float4(0.f, 0.f, 0.f, 0.f);
#pragma unroll
        for (int it = 0; it < 8; it++) {
            int idx = it * 256 + tid, n = idx & 63, k = idx >> 6;
            size_t off = (size_t)(k0 + k) * INTER + n0 + n;
            b0R[it] = B0g[off];
            b1R[it] = B1g[off];
        }
    };
    auto store_chunk = [&](int buf) {
        float* a = sA + buf * 128 * AS;
#pragma unroll
        for (int q = 0; q < 4; q++) {
            int col = acf + q * 4;
            a[ar * AS + col + 0] = tf(aR[q].x);
            a[ar * AS + col + 1] = tf(aR[q].y);
            a[ar * AS + col + 2] = tf(aR[q].z);
            a[ar * AS + col + 3] = tf(aR[q].w);
        }
        float* b0 = sB0 + buf * 64 * AS;
        float* b1 = sB1 + buf * 64 * AS;
#pragma unroll
        for (int it = 0; it < 8; it++) {
            int idx = it * 256 + tid, n = idx & 63, k = idx >> 6;
            b0[n * AS + k] = tf(b0R[it]);
            b1[n * AS + k] = tf(b1R[it]);
        }
    };

    float acc0[4][2][4] = {}, acc1[4][2][4] = {};

    auto compute = [&](int buf) {
        const float* a  = sA  + buf * 128 * AS;
        const float* b0 = sB0 + buf * 64 * AS;
        const float* b1 = sB1 + buf * 64 * AS;
#pragma unroll
        for (int ks = 0; ks < 4; ks++) {
            const int kb = ks * 8;
            uint32_t af[4][4];
#pragma unroll
            for (int i = 0; i < 4; i++) {
                int r0 = wm * 64 + i * 16 + gq;
                af[i][0] = __float_as_uint(a[r0 * AS + kb + tg]);
                af[i][1] = __float_as_uint(a[(r0 + 8) * AS + kb + tg]);
                af[i][2] = __float_as_uint(a[r0 * AS + kb + tg + 4]);
                af[i][3] = __float_as_uint(a[(r0 + 8) * AS + kb + tg + 4]);
            }
#pragma unroll
            for (int j = 0; j < 2; j++) {
                int c0 = wn * 16 + j * 8 + gq;
                uint32_t bf[2];
                bf[0] = __float_as_uint(b0[c0 * AS + kb + tg]);
                bf[1] = __float_as_uint(b0[c0 * AS + kb + tg + 4]);
#pragma unroll
                for (int i = 0; i < 4; i++) mma8(acc0[i][j], af[i], bf);
                bf[0] = __float_as_uint(b1[c0 * AS + kb + tg]);
                bf[1] = __float_as_uint(b1[c0 * AS + kb + tg + 4]);
#pragma unroll
                for (int i = 0; i < 4; i++) mma8(acc1[i][j], af[i], bf);
            }
        }
    };

    load_chunk(0); store_chunk(0); __syncthreads();
    const int C = HID / 32;
    for (int c = 0; c < C; c++) {
        int buf = c & 1;
        if (c + 1 < C) load_chunk((c + 1) * 32);
        compute(buf);
        if (c + 1 < C) store_chunk(buf ^ 1);
        __syncthreads();
    }

    // epilogue: silu(h0) * h1 scattered to g_inter
#pragma unroll
    for (int i = 0; i < 4; i++) {
#pragma unroll
        for (int h = 0; h < 2; h++) {
            int m = m0 + wm * 64 + i * 16 + gq + h * 8;
            if (m >= cnt) continue;
            int entry = g_pairs[e * NPAIRS + m];
            float* orow = g_inter + (size_t)entry * INTER + n0 + wn * 16;
#pragma unroll
            for (int j = 0; j < 2; j++) {
                float h0a = acc0[i][j][h * 2 + 0], h0b = acc0[i][j][h * 2 + 1];
                float h1a = acc1[i][j][h * 2 + 0], h1b = acc1[i][j][h * 2 + 1];
                float oa = h0a / (1.0f + __expf(-h0a)) * h1a;
                float ob = h0b / (1.0f + __expf(-h0b)) * h1b;
                *(float2*)(orow + j * 8 + tg * 2) = make_float2(oa, ob);
            }
        }
    }
}

// ---------------- GEMM2: inter @ wo[e] -------------------------------------------
// CTA tile 128M x 128N, k-chunk 32; 8 warps in 2(M) x 4(N); warp tile 64 x 32.
__global__ __launch_bounds__(256) void gemm2_mma(const float* __restrict__ wo)
{
    const int e   = blockIdx.z;
    const int cnt = g_counts[e];
    const int m0  = blockIdx.y * 128;
    if (m0 >= cnt) return;
    const int n0  = blockIdx.x * 128;
    const float* Bg = wo + (size_t)e * INTER * HID;

    extern __shared__ float sm[];
    float* sA = sm;                     // [2][128*AS]
    float* sB = sm + 2 * 128 * AS;      // [2][128*AS]

    const int tid = threadIdx.x, lane = tid & 31, wid = tid >> 5;
    const int wm = wid >> 2, wn = wid & 3;
    const int gq = lane >> 2, tg = lane & 3;

    const int ar = tid >> 1, acf = (tid & 1) * 16;
    const float* arow = nullptr;
    {
        int mg = m0 + ar;
        if (mg < cnt) arow = g_inter + (size_t)g_pairs[e * NPAIRS + mg] * INTER;
    }

    float4 aR[4];
    float  bR[16];

    auto load_chunk = [&](int k0) {
#pragma unroll
        for (int q = 0; q < 4; q++)
            aR[q] = arow ? *(const float4*)(arow + k0 + acf + q * 4)
                         : make_float4(0.f, 0.f, 0.f, 0.f);
#pragma unroll
        for (int it = 0; it < 16; it++) {
            int idx = it * 256 + tid, n = idx & 127, k = idx >> 7;
            bR[it] = Bg[(size_t)(k0 + k) * HID + n0 + n];
        }
    };
    auto store_chunk = [&](int buf) {
        float* a = sA + buf * 128 * AS;
#pragma unroll
        for (int q = 0; q < 4; q++) {
            int col = acf + q * 4;
            a[ar * AS + col + 0] = tf(aR[q].x);
            a[ar * AS + col + 1] = tf(aR[q].y);
            a[ar * AS + col + 2] = tf(aR[q].z);
            a[ar * AS + col + 3] = tf(aR[q].w);
        }
        float* b = sB + buf * 128 * AS;
#pragma unroll
        for (int it = 0; it < 16; it++) {
            int idx = it * 256 + tid, n = idx & 127, k = idx >> 7;
            b[n * AS + k] = tf(bR[it]);
        }
    };

    float acc[4][4][4] = {};

    auto compute = [&](int buf) {
        const float* a = sA + buf * 128 * AS;
        const float* b = sB + buf * 128 * AS;
#pragma unroll
        for (int ks = 0; ks < 4; ks++) {
            const int kb = ks * 8;
            uint32_t af[4][4];
#pragma unroll
            for (int i = 0; i < 4; i++) {
                int r0 = wm * 64 + i * 16 + gq;
                af[i][0] = __float_as_uint(a[r0 * AS + kb + tg]);
                af[i][1] = __float_as_uint(a[(r0 + 8) * AS + kb + tg]);
                af[i][2] = __float_as_uint(a[r0 * AS + kb + tg + 4]);
                af[i][3] = __float_as_uint(a[(r0 + 8) * AS + kb + tg + 4]);
            }
#pragma unroll
            for (int j = 0; j < 4; j++) {
                int c0 = wn * 32 + j * 8 + gq;
                uint32_t bf[2];
                bf[0] = __float_as_uint(b[c0 * AS + kb + tg]);
                bf[1] = __float_as_uint(b[c0 * AS + kb + tg + 4]);
#pragma unroll
                for (int i = 0; i < 4; i++) mma8(acc[i][j], af[i], bf);
            }
        }
    };

    load_chunk(0); store_chunk(0); __syncthreads();
    const int C = INTER / 32;
    for (int c = 0; c < C; c++) {
        int buf = c & 1;
        if (c + 1 < C) load_chunk((c + 1) * 32);
        compute(buf);
        if (c + 1 < C) store_chunk(buf ^ 1);
        __syncthreads();
    }

#pragma unroll
    for (int i = 0; i < 4; i++) {
#pragma unroll
        for (int h = 0; h < 2; h++) {
            int m = m0 + wm * 64 + i * 16 + gq + h * 8;
            if (m >= cnt) continue;
            int entry = g_pairs[e * NPAIRS + m];
            float* yrow = g_y + (size_t)entry * HID + n0 + wn * 32;
#pragma unroll
            for (int j = 0; j < 4; j++)
                *(float2*)(yrow + j * 8 + tg * 2) =
                    make_float2(acc[i][j][h * 2 + 0], acc[i][j][h * 2 + 1]);
        }
    }
}

// ---------------- combine ----------------------------------------------------------
__global__ void combine_kernel(float* __restrict__ out)
{
    int t = blockIdx.x;
    float w0 = g_w[2 * t + 0];
    float w1 = g_w[2 * t + 1];
    const float4* y0 = (const float4*)(g_y + (size_t)(2 * t + 0) * HID);
    const float4* y1 = (const float4*)(g_y + (size_t)(2 * t + 1) * HID);
    float4* o = (float4*)(out + (size_t)t * HID);
    for (int h = threadIdx.x; h < HID / 4; h += blockDim.x) {
        float4 a = y0[h], b = y1[h];
        o[h] = make_float4(w0 * a.x + w1 * b.x, w0 * a.y + w1 * b.y,
                           w0 * a.z + w1 * b.z, w0 * a.w + w1 * b.w);
    }
}

// ---------------- launch -------------------------------------------------------------
extern "C" void kernel_launch(void* const* d_in, const int* in_sizes, int n_in,
                              void* d_out, int out_size)
{
    const float* x      = (const float*)d_in[0];
    const float* logits = (const float*)d_in[1];
    const float* wi0    = (const float*)d_in[2];
    const float* wi1    = (const float*)d_in[3];
    const float* wo     = (const float*)d_in[4];
    float* out          = (float*)d_out;

    const int g1_smem = (2 * 128 * AS + 4 * 64 * AS) * 4;   // 73728 B
    const int g2_smem = (4 * 128 * AS) * 4;                  // 73728 B
    cudaFuncSetAttribute(gemm1_mma, cudaFuncAttributeMaxDynamicSharedMemorySize, g1_smem);
    cudaFuncSetAttribute(gemm2_mma, cudaFuncAttributeMaxDynamicSharedMemorySize, g2_smem);

    zero_counts_kernel<<<1, 32>>>();
    route_kernel<<<T_TOKENS / 256, 256>>>(logits);

    dim3 g1(INTER / 64, NPAIRS / 128, NEXP);   // (32, 32, 8)
    gemm1_mma<<<g1, 256, g1_smem>>>(x, wi0, wi1);

    dim3 g2(HID / 128, NPAIRS / 128, NEXP);    // (8, 32, 8)
    gemm2_mma<<<g2, 256, g2_smem>>>(wo);

    combine_kernel<<<T_TOKENS, 256>>>(out);
}

// round 5
// speedup vs baseline: 3.0850x; 1.4872x over previous
#include <cuda_runtime.h>
#include <math.h>
#include <stdint.h>

#define T_TOKENS 2048
#define HID      1024
#define INTER    2048
#define NEXP     8
#define NPAIRS   (T_TOKENS * 2)

// ---------------- scratch -----------------------------------------------------
__device__ int   g_counts[NEXP];
__device__ int   g_pairs[NEXP * NPAIRS];
__device__ float g_w[NPAIRS];
__device__ float g_inter[(size_t)NPAIRS * INTER]; // 32 MB

// ---------------- helpers -------------------------------------------------------
__device__ __forceinline__ float tf(float f) {
    uint32_t r;
    asm("cvt.rna.tf32.f32 %0, %1;" : "=r"(r) : "f"(f));
    return __uint_as_float(r);
}
__device__ __forceinline__ uint32_t smem_u32(const void* p) {
    uint32_t a;
    asm("{ .reg .u64 t; cvta.to.shared.u64 t, %1; cvt.u32.u64 %0, t; }" : "=r"(a) : "l"(p));
    return a;
}
__device__ __forceinline__ void mma8(float* d, const uint32_t* a, const uint32_t* b) {
    asm volatile(
        "mma.sync.aligned.m16n8k8.row.col.f32.tf32.tf32.f32 "
        "{%0,%1,%2,%3}, {%4,%5,%6,%7}, {%8,%9}, {%0,%1,%2,%3};"
        : "+f"(d[0]), "+f"(d[1]), "+f"(d[2]), "+f"(d[3])
        : "r"(a[0]), "r"(a[1]), "r"(a[2]), "r"(a[3]), "r"(b[0]), "r"(b[1]));
}
__device__ __forceinline__ void ldsm4(uint32_t* r, uint32_t addr) {
    asm volatile("ldmatrix.sync.aligned.m8n8.x4.shared.b16 {%0,%1,%2,%3}, [%4];"
        : "=r"(r[0]), "=r"(r[1]), "=r"(r[2]), "=r"(r[3]) : "r"(addr));
}

// ---------------- routing --------------------------------------------------------
__global__ void zero_counts_kernel() {
    if (threadIdx.x < NEXP) g_counts[threadIdx.x] = 0;
}

__global__ void route_kernel(const float* __restrict__ logits) {
    int t = blockIdx.x * blockDim.x + threadIdx.x;
    if (t >= T_TOKENS) return;
    float l[NEXP];
#pragma unroll
    for (int e = 0; e < NEXP; e++) l[e] = logits[t * NEXP + e];
    int i0 = 0; float v0 = l[0];
#pragma unroll
    for (int e = 1; e < NEXP; e++) if (l[e] > v0) { v0 = l[e]; i0 = e; }
    int i1 = -1; float v1 = -__FLT_MAX__;
#pragma unroll
    for (int e = 0; e < NEXP; e++) {
        if (e == i0) continue;
        if (l[e] > v1) { v1 = l[e]; i1 = e; }
    }
    float e1 = expf(v1 - v0);
    float s  = 1.0f + e1;
    g_w[t * 2 + 0] = 1.0f / s;
    g_w[t * 2 + 1] = e1 / s;
    int p0 = atomicAdd(&g_counts[i0], 1);
    g_pairs[i0 * NPAIRS + p0] = t * 2 + 0;
    int p1 = atomicAdd(&g_counts[i1], 1);
    g_pairs[i1 * NPAIRS + p1] = t * 2 + 1;
}

__global__ void zero_out_kernel(float* __restrict__ out) {
    int i = blockIdx.x * blockDim.x + threadIdx.x;
    ((float4*)out)[i] = make_float4(0.f, 0.f, 0.f, 0.f);
}

// ---------------- GEMM1: x @ {wi0, wi1}[e] + fused SwiGLU ------------------------
// CTA 128M x 64N(per matrix), k-chunk 32, double buffered, SW128-swizzled smem.
// 8 warps 2(M)x4(N); warp tile 64x16 per matrix; tf32 m16n8k8 + ldmatrix.
__global__ __launch_bounds__(256) void gemm1_mma(
    const float* __restrict__ x,
    const float* __restrict__ wi0,
    const float* __restrict__ wi1)
{
    const int e   = blockIdx.z;
    const int cnt = g_counts[e];
    const int m0  = blockIdx.y * 128;
    if (m0 >= cnt) return;
    const int n0  = blockIdx.x * 64;
    const float* B0g = wi0 + (size_t)e * HID * INTER;
    const float* B1g = wi1 + (size_t)e * HID * INTER;

    extern __shared__ float smf[];
    unsigned char* smc = (unsigned char*)smf;          // A:[0,32768) B0:[32768,49152) B1:[49152,65536)
    const uint32_t sb = smem_u32(smc);

    const int tid = threadIdx.x, lane = tid & 31, wid = tid >> 5;
    const int wm = wid >> 2, wn = wid & 3;
    const int gq = lane >> 2, tg = lane & 3;
    const int l7 = lane & 7;

    // ldmatrix per-lane bases
    const uint32_t aLane = (uint32_t)(wm * 64 + l7 + ((lane >> 3) & 1) * 8) * 128u;
    const int      c4a   = lane >> 4;                  // chunk offset for A (0/1)
    const uint32_t bLane = (uint32_t)(wn * 16 + ((lane >> 4) & 1) * 8 + l7) * 128u;
    const int      c4b   = (lane >> 3) & 1;

    // A gather
    const int ar = tid >> 1, side = tid & 1;
    const float* arow = nullptr;
    {
        int mg = m0 + ar;
        if (mg < cnt) arow = x + (size_t)(g_pairs[e * NPAIRS + mg] >> 1) * HID;
    }
    // B staging mapping
    const int bn = tid & 63, bkg = (tid >> 6) * 8;

    float4 aR[4];
    float  b0R[8], b1R[8];

    auto load_chunk = [&](int k0) {
#pragma unroll
        for (int q = 0; q < 4; q++)
            aR[q] = arow ? *(const float4*)(arow + k0 + side * 16 + q * 4)
                         : make_float4(0.f, 0.f, 0.f, 0.f);
#pragma unroll
        for (int kk = 0; kk < 8; kk++) {
            size_t off = (size_t)(k0 + bkg + kk) * INTER + n0 + bn;
            b0R[kk] = B0g[off];
            b1R[kk] = B1g[off];
        }
    };
    auto store_chunk = [&](int buf) {
        unsigned char* a = smc + buf * 16384;
#pragma unroll
        for (int q = 0; q < 4; q++) {
            uint32_t byte = (uint32_t)ar * 128u + (uint32_t)(((side * 4 + q) ^ (ar & 7)) << 4);
            *(float4*)(a + byte) = make_float4(tf(aR[q].x), tf(aR[q].y), tf(aR[q].z), tf(aR[q].w));
        }
        unsigned char* b0 = smc + 32768 + buf * 8192;
        unsigned char* b1 = smc + 49152 + buf * 8192;
#pragma unroll
        for (int g = 0; g < 2; g++) {
            uint32_t byte = (uint32_t)bn * 128u + (uint32_t)((((bkg >> 2) + g) ^ (bn & 7)) << 4);
            *(float4*)(b0 + byte) = make_float4(tf(b0R[g*4]), tf(b0R[g*4+1]), tf(b0R[g*4+2]), tf(b0R[g*4+3]));
            *(float4*)(b1 + byte) = make_float4(tf(b1R[g*4]), tf(b1R[g*4+1]), tf(b1R[g*4+2]), tf(b1R[g*4+3]));
        }
    };

    float acc0[4][2][4] = {}, acc1[4][2][4] = {};

    auto compute = [&](int buf) {
        const uint32_t ab  = sb + buf * 16384 + aLane;
        const uint32_t b0b = sb + 32768 + buf * 8192 + bLane;
        const uint32_t b1b = b0b + 16384;
#pragma unroll
        for (int ks = 0; ks < 4; ks++) {
            const int kc = ks * 2;   // kb>>2
            const uint32_t ca = (uint32_t)(((kc + c4a) ^ l7) << 4);
            const uint32_t cb = (uint32_t)(((kc + c4b) ^ l7) << 4);
            uint32_t af[4][4];
#pragma unroll
            for (int i = 0; i < 4; i++) ldsm4(af[i], ab + i * 2048 + ca);
            uint32_t f0[4], f1[4];
            ldsm4(f0, b0b + cb);
            ldsm4(f1, b1b + cb);
#pragma unroll
            for (int j = 0; j < 2; j++)
#pragma unroll
                for (int i = 0; i < 4; i++) {
                    mma8(acc0[i][j], af[i], f0 + j * 2);
                    mma8(acc1[i][j], af[i], f1 + j * 2);
                }
        }
    };

    load_chunk(0); store_chunk(0); __syncthreads();
    const int C = HID / 32;
    for (int c = 0; c < C; c++) {
        int buf = c & 1;
        if (c + 1 < C) load_chunk((c + 1) * 32);
        compute(buf);
        if (c + 1 < C) store_chunk(buf ^ 1);
        __syncthreads();
    }

    // epilogue: silu(h0) * h1 -> g_inter
#pragma unroll
    for (int i = 0; i < 4; i++) {
#pragma unroll
        for (int h = 0; h < 2; h++) {
            int m = m0 + wm * 64 + i * 16 + gq + h * 8;
            if (m >= cnt) continue;
            int entry = g_pairs[e * NPAIRS + m];
            float* orow = g_inter + (size_t)entry * INTER + n0 + wn * 16;
#pragma unroll
            for (int j = 0; j < 2; j++) {
                float h0a = acc0[i][j][h * 2 + 0], h0b = acc0[i][j][h * 2 + 1];
                float h1a = acc1[i][j][h * 2 + 0], h1b = acc1[i][j][h * 2 + 1];
                float oa = h0a / (1.0f + __expf(-h0a)) * h1a;
                float ob = h0b / (1.0f + __expf(-h0b)) * h1b;
                *(float2*)(orow + j * 8 + tg * 2) = make_float2(oa, ob);
            }
        }
    }
}

// ---------------- GEMM2: inter @ wo[e], fused weighted combine -------------------
// CTA 128M x 128N, k-chunk 32; 8 warps 2(M)x4(N); warp tile 64x32.
__global__ __launch_bounds__(256) void gemm2_mma(const float* __restrict__ wo,
                                                 float* __restrict__ out)
{
    const int e   = blockIdx.z;
    const int cnt = g_counts[e];
    const int m0  = blockIdx.y * 128;
    if (m0 >= cnt) return;
    const int n0  = blockIdx.x * 128;
    const float* Bg = wo + (size_t)e * INTER * HID;

    extern __shared__ float smf[];
    unsigned char* smc = (unsigned char*)smf;          // A:[0,32768) B:[32768,65536)
    const uint32_t sb = smem_u32(smc);

    const int tid = threadIdx.x, lane = tid & 31, wid = tid >> 5;
    const int wm = wid >> 2, wn = wid & 3;
    const int gq = lane >> 2, tg = lane & 3;
    const int l7 = lane & 7;

    const uint32_t aLane = (uint32_t)(wm * 64 + l7 + ((lane >> 3) & 1) * 8) * 128u;
    const int      c4a   = lane >> 4;
    const uint32_t bLane = (uint32_t)(wn * 32 + ((lane >> 4) & 1) * 8 + l7) * 128u;
    const int      c4b   = (lane >> 3) & 1;

    const int ar = tid >> 1, side = tid & 1;
    const float* arow = nullptr;
    {
        int mg = m0 + ar;
        if (mg < cnt) arow = g_inter + (size_t)g_pairs[e * NPAIRS + mg] * INTER;
    }
    const int bn = tid & 127, bkg = (tid >> 7) * 16;

    float4 aR[4];
    float  bR[16];

    auto load_chunk = [&](int k0) {
#pragma unroll
        for (int q = 0; q < 4; q++)
            aR[q] = arow ? *(const float4*)(arow + k0 + side * 16 + q * 4)
                         : make_float4(0.f, 0.f, 0.f, 0.f);
#pragma unroll
        for (int kk = 0; kk < 16; kk++)
            bR[kk] = Bg[(size_t)(k0 + bkg + kk) * HID + n0 + bn];
    };
    auto store_chunk = [&](int buf) {
        unsigned char* a = smc + buf * 16384;
#pragma unroll
        for (int q = 0; q < 4; q++) {
            uint32_t byte = (uint32_t)ar * 128u + (uint32_t)(((side * 4 + q) ^ (ar & 7)) << 4);
            *(float4*)(a + byte) = make_float4(tf(aR[q].x), tf(aR[q].y), tf(aR[q].z), tf(aR[q].w));
        }
        unsigned char* b = smc + 32768 + buf * 16384;
#pragma unroll
        for (int g = 0; g < 4; g++) {
            uint32_t byte = (uint32_t)bn * 128u + (uint32_t)((((bkg >> 2) + g) ^ (bn & 7)) << 4);
            *(float4*)(b + byte) = make_float4(tf(bR[g*4]), tf(bR[g*4+1]), tf(bR[g*4+2]), tf(bR[g*4+3]));
        }
    };

    float acc[4][4][4] = {};

    auto compute = [&](int buf) {
        const uint32_t ab = sb + buf * 16384 + aLane;
        const uint32_t bb = sb + 32768 + buf * 16384 + bLane;
#pragma unroll
        for (int ks = 0; ks < 4; ks++) {
            const int kc = ks * 2;
            const uint32_t ca = (uint32_t)(((kc + c4a) ^ l7) << 4);
            const uint32_t cb = (uint32_t)(((kc + c4b) ^ l7) << 4);
            uint32_t af[4][4];
#pragma unroll
            for (int i = 0; i < 4; i++) ldsm4(af[i], ab + i * 2048 + ca);
#pragma unroll
            for (int jp = 0; jp < 2; jp++) {
                uint32_t bf[4];
                ldsm4(bf, bb + jp * 2048 + cb);
#pragma unroll
                for (int i = 0; i < 4; i++) {
                    mma8(acc[i][jp * 2 + 0], af[i], bf + 0);
                    mma8(acc[i][jp * 2 + 1], af[i], bf + 2);
                }
            }
        }
    };

    load_chunk(0); store_chunk(0); __syncthreads();
    const int C = INTER / 32;
    for (int c = 0; c < C; c++) {
        int buf = c & 1;
        if (c + 1 < C) load_chunk((c + 1) * 32);
        compute(buf);
        if (c + 1 < C) store_chunk(buf ^ 1);
        __syncthreads();
    }

    // fused combine: out[token] += w * y  (bitwise deterministic: a+b == b+a)
#pragma unroll
    for (int i = 0; i < 4; i++) {
#pragma unroll
        for (int h = 0; h < 2; h++) {
            int m = m0 + wm * 64 + i * 16 + gq + h * 8;
            if (m >= cnt) continue;
            int entry = g_pairs[e * NPAIRS + m];
            float w = g_w[entry];
            float* base = out + (size_t)(entry >> 1) * HID + n0 + wn * 32 + tg * 2;
#pragma unroll
            for (int j = 0; j < 4; j++) {
                atomicAdd(base + j * 8 + 0, w * acc[i][j][h * 2 + 0]);
                atomicAdd(base + j * 8 + 1, w * acc[i][j][h * 2 + 1]);
            }
        }
    }
}

// ---------------- launch -------------------------------------------------------------
extern "C" void kernel_launch(void* const* d_in, const int* in_sizes, int n_in,
                              void* d_out, int out_size)
{
    const float* x      = (const float*)d_in[0];
    const float* logits = (const float*)d_in[1];
    const float* wi0    = (const float*)d_in[2];
    const float* wi1    = (const float*)d_in[3];
    const float* wo     = (const float*)d_in[4];
    float* out          = (float*)d_out;

    const int smem = 65536;
    cudaFuncSetAttribute(gemm1_mma, cudaFuncAttributeMaxDynamicSharedMemorySize, smem);
    cudaFuncSetAttribute(gemm2_mma, cudaFuncAttributeMaxDynamicSharedMemorySize, smem);

    zero_counts_kernel<<<1, 32>>>();
    route_kernel<<<T_TOKENS / 256, 256>>>(logits);
    zero_out_kernel<<<(T_TOKENS * HID / 4) / 256, 256>>>(out);

    dim3 g1(INTER / 64, NPAIRS / 128, NEXP);   // (32, 32, 8)
    gemm1_mma<<<g1, 256, smem>>>(x, wi0, wi1);

    dim3 g2(HID / 128, NPAIRS / 128, NEXP);    // (8, 32, 8)
    gemm2_mma<<<g2, 256, smem>>>(wo, out);
}

// round 6
// speedup vs baseline: 3.3055x; 1.0715x over previous
#include <cuda_runtime.h>
#include <math.h>
#include <stdint.h>

#define T_TOKENS 2048
#define HID      1024
#define INTER    2048
#define NEXP     8
#define NPAIRS   (T_TOKENS * 2)

// ---------------- scratch -----------------------------------------------------
__device__ int   g_counts[NEXP];
__device__ int   g_pairs[NEXP * NPAIRS];
__device__ float g_w[NPAIRS];
__device__ float g_inter[(size_t)NPAIRS * INTER]; // 32 MB

// ---------------- helpers -------------------------------------------------------
__device__ __forceinline__ float tf(float f) {
    uint32_t r;
    asm("cvt.rna.tf32.f32 %0, %1;" : "=r"(r) : "f"(f));
    return __uint_as_float(r);
}
__device__ __forceinline__ uint32_t smem_u32(const void* p) {
    uint32_t a;
    asm("{ .reg .u64 t; cvta.to.shared.u64 t, %1; cvt.u32.u64 %0, t; }" : "=r"(a) : "l"(p));
    return a;
}
__device__ __forceinline__ void mma8(float* d, const uint32_t* a, const uint32_t* b) {
    asm volatile(
        "mma.sync.aligned.m16n8k8.row.col.f32.tf32.tf32.f32 "
        "{%0,%1,%2,%3}, {%4,%5,%6,%7}, {%8,%9}, {%0,%1,%2,%3};"
        : "+f"(d[0]), "+f"(d[1]), "+f"(d[2]), "+f"(d[3])
        : "r"(a[0]), "r"(a[1]), "r"(a[2]), "r"(a[3]), "r"(b[0]), "r"(b[1]));
}
__device__ __forceinline__ void ldsm4(uint32_t* r, uint32_t addr) {
    asm volatile("ldmatrix.sync.aligned.m8n8.x4.shared.b16 {%0,%1,%2,%3}, [%4];"
        : "=r"(r[0]), "=r"(r[1]), "=r"(r[2]), "=r"(r[3]) : "r"(addr));
}

// ---------------- routing --------------------------------------------------------
__global__ void zero_counts_kernel() {
    if (threadIdx.x < NEXP) g_counts[threadIdx.x] = 0;
}

__global__ void route_kernel(const float* __restrict__ logits) {
    int t = blockIdx.x * blockDim.x + threadIdx.x;
    if (t >= T_TOKENS) return;
    float l[NEXP];
#pragma unroll
    for (int e = 0; e < NEXP; e++) l[e] = logits[t * NEXP + e];
    int i0 = 0; float v0 = l[0];
#pragma unroll
    for (int e = 1; e < NEXP; e++) if (l[e] > v0) { v0 = l[e]; i0 = e; }
    int i1 = -1; float v1 = -__FLT_MAX__;
#pragma unroll
    for (int e = 0; e < NEXP; e++) {
        if (e == i0) continue;
        if (l[e] > v1) { v1 = l[e]; i1 = e; }
    }
    float e1 = expf(v1 - v0);
    float s  = 1.0f + e1;
    g_w[t * 2 + 0] = 1.0f / s;
    g_w[t * 2 + 1] = e1 / s;
    int p0 = atomicAdd(&g_counts[i0], 1);
    g_pairs[i0 * NPAIRS + p0] = t * 2 + 0;
    int p1 = atomicAdd(&g_counts[i1], 1);
    g_pairs[i1 * NPAIRS + p1] = t * 2 + 1;
}

__global__ void zero_out_kernel(float* __restrict__ out) {
    int i = blockIdx.x * blockDim.x + threadIdx.x;
    ((float4*)out)[i] = make_float4(0.f, 0.f, 0.f, 0.f);
}

// ---------------- GEMM1: x @ {wi0, wi1}[e] + fused SwiGLU ------------------------
// CTA 128M x 128N (per matrix), k-chunk 32, double buffered, SW128 smem.
// 8 warps 2(M)x4(N); warp tile 64x32 per matrix; tf32 m16n8k8 + ldmatrix.
__global__ __launch_bounds__(256, 1) void gemm1_mma(
    const float* __restrict__ x,
    const float* __restrict__ wi0,
    const float* __restrict__ wi1)
{
    const int e   = blockIdx.z;
    const int cnt = g_counts[e];
    const int m0  = blockIdx.y * 128;
    if (m0 >= cnt) return;
    const int n0  = blockIdx.x * 128;
    const float* B0g = wi0 + (size_t)e * HID * INTER;
    const float* B1g = wi1 + (size_t)e * HID * INTER;

    extern __shared__ float smf[];
    unsigned char* smc = (unsigned char*)smf;   // A:[0,32K) B0:[32K,64K) B1:[64K,96K)
    const uint32_t sb = smem_u32(smc);

    const int tid = threadIdx.x, lane = tid & 31, wid = tid >> 5;
    const int wm = wid >> 2, wn = wid & 3;
    const int gq = lane >> 2, tg = lane & 3;
    const int l7 = lane & 7;

    const uint32_t aLane = (uint32_t)(wm * 64 + l7 + ((lane >> 3) & 1) * 8) * 128u;
    const int      c4a   = lane >> 4;
    const uint32_t bLane = (uint32_t)(wn * 32 + ((lane >> 4) & 1) * 8 + l7) * 128u;
    const int      c4b   = (lane >> 3) & 1;

    // A gather
    const int ar = tid >> 1, side = tid & 1;
    const float* arow = nullptr;
    {
        int mg = m0 + ar;
        if (mg < cnt) arow = x + (size_t)(g_pairs[e * NPAIRS + mg] >> 1) * HID;
    }
    // B staging: 128 n-cols, 32 k-rows, 16 elems per thread per matrix
    const int bn = tid & 127, bkg = (tid >> 7) * 16;

    float4 aR[4];
    float  b0R[16], b1R[16];

    auto load_chunk = [&](int k0) {
#pragma unroll
        for (int q = 0; q < 4; q++)
            aR[q] = arow ? *(const float4*)(arow + k0 + side * 16 + q * 4)
                         : make_float4(0.f, 0.f, 0.f, 0.f);
#pragma unroll
        for (int kk = 0; kk < 16; kk++) {
            size_t off = (size_t)(k0 + bkg + kk) * INTER + n0 + bn;
            b0R[kk] = B0g[off];
            b1R[kk] = B1g[off];
        }
    };
    auto store_chunk = [&](int buf) {
        unsigned char* a = smc + buf * 16384;
#pragma unroll
        for (int q = 0; q < 4; q++) {
            uint32_t byte = (uint32_t)ar * 128u + (uint32_t)(((side * 4 + q) ^ (ar & 7)) << 4);
            *(float4*)(a + byte) = make_float4(tf(aR[q].x), tf(aR[q].y), tf(aR[q].z), tf(aR[q].w));
        }
        unsigned char* b0 = smc + 32768 + buf * 16384;
        unsigned char* b1 = smc + 65536 + buf * 16384;
#pragma unroll
        for (int g = 0; g < 4; g++) {
            uint32_t byte = (uint32_t)bn * 128u + (uint32_t)((((bkg >> 2) + g) ^ (bn & 7)) << 4);
            *(float4*)(b0 + byte) = make_float4(tf(b0R[g*4]), tf(b0R[g*4+1]), tf(b0R[g*4+2]), tf(b0R[g*4+3]));
            *(float4*)(b1 + byte) = make_float4(tf(b1R[g*4]), tf(b1R[g*4+1]), tf(b1R[g*4+2]), tf(b1R[g*4+3]));
        }
    };

    float acc0[4][4][4] = {}, acc1[4][4][4] = {};

    auto compute = [&](int buf) {
        const uint32_t ab  = sb + buf * 16384 + aLane;
        const uint32_t b0b = sb + 32768 + buf * 16384 + bLane;
        const uint32_t b1b = sb + 65536 + buf * 16384 + bLane;
#pragma unroll
        for (int ks = 0; ks < 4; ks++) {
            const int kc = ks * 2;
            const uint32_t ca = (uint32_t)(((kc + c4a) ^ l7) << 4);
            const uint32_t cb = (uint32_t)(((kc + c4b) ^ l7) << 4);
            uint32_t af[4][4];
#pragma unroll
            for (int i = 0; i < 4; i++) ldsm4(af[i], ab + i * 2048 + ca);
#pragma unroll
            for (int jp = 0; jp < 2; jp++) {
                uint32_t f0[4], f1[4];
                ldsm4(f0, b0b + jp * 2048 + cb);
                ldsm4(f1, b1b + jp * 2048 + cb);
#pragma unroll
                for (int i = 0; i < 4; i++) {
                    mma8(acc0[i][jp * 2 + 0], af[i], f0 + 0);
                    mma8(acc0[i][jp * 2 + 1], af[i], f0 + 2);
                    mma8(acc1[i][jp * 2 + 0], af[i], f1 + 0);
                    mma8(acc1[i][jp * 2 + 1], af[i], f1 + 2);
                }
            }
        }
    };

    load_chunk(0); store_chunk(0); __syncthreads();
    const int C = HID / 32;
    for (int c = 0; c < C; c++) {
        int buf = c & 1;
        if (c + 1 < C) load_chunk((c + 1) * 32);
        compute(buf);
        if (c + 1 < C) store_chunk(buf ^ 1);
        __syncthreads();
    }

    // epilogue: silu(h0) * h1 -> g_inter
#pragma unroll
    for (int i = 0; i < 4; i++) {
#pragma unroll
        for (int h = 0; h < 2; h++) {
            int m = m0 + wm * 64 + i * 16 + gq + h * 8;
            if (m >= cnt) continue;
            int entry = g_pairs[e * NPAIRS + m];
            float* orow = g_inter + (size_t)entry * INTER + n0 + wn * 32;
#pragma unroll
            for (int j = 0; j < 4; j++) {
                float h0a = acc0[i][j][h * 2 + 0], h0b = acc0[i][j][h * 2 + 1];
                float h1a = acc1[i][j][h * 2 + 0], h1b = acc1[i][j][h * 2 + 1];
                float oa = h0a / (1.0f + __expf(-h0a)) * h1a;
                float ob = h0b / (1.0f + __expf(-h0b)) * h1b;
                *(float2*)(orow + j * 8 + tg * 2) = make_float2(oa, ob);
            }
        }
    }
}

// ---------------- GEMM2: inter @ wo[e], fused weighted combine -------------------
// CTA 128M x 128N, k-chunk 32; 8 warps 2(M)x4(N); warp tile 64x32.
__global__ __launch_bounds__(256) void gemm2_mma(const float* __restrict__ wo,
                                                 float* __restrict__ out)
{
    const int e   = blockIdx.z;
    const int cnt = g_counts[e];
    const int m0  = blockIdx.y * 128;
    if (m0 >= cnt) return;
    const int n0  = blockIdx.x * 128;
    const float* Bg = wo + (size_t)e * INTER * HID;

    extern __shared__ float smf[];
    unsigned char* smc = (unsigned char*)smf;   // A:[0,32K) B:[32K,64K)
    const uint32_t sb = smem_u32(smc);

    const int tid = threadIdx.x, lane = tid & 31, wid = tid >> 5;
    const int wm = wid >> 2, wn = wid & 3;
    const int gq = lane >> 2, tg = lane & 3;
    const int l7 = lane & 7;

    const uint32_t aLane = (uint32_t)(wm * 64 + l7 + ((lane >> 3) & 1) * 8) * 128u;
    const int      c4a   = lane >> 4;
    const uint32_t bLane = (uint32_t)(wn * 32 + ((lane >> 4) & 1) * 8 + l7) * 128u;
    const int      c4b   = (lane >> 3) & 1;

    const int ar = tid >> 1, side = tid & 1;
    const float* arow = nullptr;
    {
        int mg = m0 + ar;
        if (mg < cnt) arow = g_inter + (size_t)g_pairs[e * NPAIRS + mg] * INTER;
    }
    const int bn = tid & 127, bkg = (tid >> 7) * 16;

    float4 aR[4];
    float  bR[16];

    auto load_chunk = [&](int k0) {
#pragma unroll
        for (int q = 0; q < 4; q++)
            aR[q] = arow ? *(const float4*)(arow + k0 + side * 16 + q * 4)
                         : make_float4(0.f, 0.f, 0.f, 0.f);
#pragma unroll
        for (int kk = 0; kk < 16; kk++)
            bR[kk] = Bg[(size_t)(k0 + bkg + kk) * HID + n0 + bn];
    };
    auto store_chunk = [&](int buf) {
        unsigned char* a = smc + buf * 16384;
#pragma unroll
        for (int q = 0; q < 4; q++) {
            uint32_t byte = (uint32_t)ar * 128u + (uint32_t)(((side * 4 + q) ^ (ar & 7)) << 4);
            *(float4*)(a + byte) = make_float4(tf(aR[q].x), tf(aR[q].y), tf(aR[q].z), tf(aR[q].w));
        }
        unsigned char* b = smc + 32768 + buf * 16384;
#pragma unroll
        for (int g = 0; g < 4; g++) {
            uint32_t byte = (uint32_t)bn * 128u + (uint32_t)((((bkg >> 2) + g) ^ (bn & 7)) << 4);
            *(float4*)(b + byte) = make_float4(tf(bR[g*4]), tf(bR[g*4+1]), tf(bR[g*4+2]), tf(bR[g*4+3]));
        }
    };

    float acc[4][4][4] = {};

    auto compute = [&](int buf) {
        const uint32_t ab = sb + buf * 16384 + aLane;
        const uint32_t bb = sb + 32768 + buf * 16384 + bLane;
#pragma unroll
        for (int ks = 0; ks < 4; ks++) {
            const int kc = ks * 2;
            const uint32_t ca = (uint32_t)(((kc + c4a) ^ l7) << 4);
            const uint32_t cb = (uint32_t)(((kc + c4b) ^ l7) << 4);
            uint32_t af[4][4];
#pragma unroll
            for (int i = 0; i < 4; i++) ldsm4(af[i], ab + i * 2048 + ca);
#pragma unroll
            for (int jp = 0; jp < 2; jp++) {
                uint32_t bf[4];
                ldsm4(bf, bb + jp * 2048 + cb);
#pragma unroll
                for (int i = 0; i < 4; i++) {
                    mma8(acc[i][jp * 2 + 0], af[i], bf + 0);
                    mma8(acc[i][jp * 2 + 1], af[i], bf + 2);
                }
            }
        }
    };

    load_chunk(0); store_chunk(0); __syncthreads();
    const int C = INTER / 32;
    for (int c = 0; c < C; c++) {
        int buf = c & 1;
        if (c + 1 < C) load_chunk((c + 1) * 32);
        compute(buf);
        if (c + 1 < C) store_chunk(buf ^ 1);
        __syncthreads();
    }

    // fused combine: out[token] += w * y  (bitwise deterministic: a+b == b+a)
#pragma unroll
    for (int i = 0; i < 4; i++) {
#pragma unroll
        for (int h = 0; h < 2; h++) {
            int m = m0 + wm * 64 + i * 16 + gq + h * 8;
            if (m >= cnt) continue;
            int entry = g_pairs[e * NPAIRS + m];
            float w = g_w[entry];
            float* base = out + (size_t)(entry >> 1) * HID + n0 + wn * 32 + tg * 2;
#pragma unroll
            for (int j = 0; j < 4; j++) {
                atomicAdd(base + j * 8 + 0, w * acc[i][j][h * 2 + 0]);
                atomicAdd(base + j * 8 + 1, w * acc[i][j][h * 2 + 1]);
            }
        }
    }
}

// ---------------- launch -------------------------------------------------------------
extern "C" void kernel_launch(void* const* d_in, const int* in_sizes, int n_in,
                              void* d_out, int out_size)
{
    const float* x      = (const float*)d_in[0];
    const float* logits = (const float*)d_in[1];
    const float* wi0    = (const float*)d_in[2];
    const float* wi1    = (const float*)d_in[3];
    const float* wo     = (const float*)d_in[4];
    float* out          = (float*)d_out;

    const int g1_smem = 98304;
    const int g2_smem = 65536;
    cudaFuncSetAttribute(gemm1_mma, cudaFuncAttributeMaxDynamicSharedMemorySize, g1_smem);
    cudaFuncSetAttribute(gemm2_mma, cudaFuncAttributeMaxDynamicSharedMemorySize, g2_smem);

    zero_counts_kernel<<<1, 32>>>();
    route_kernel<<<T_TOKENS / 256, 256>>>(logits);
    zero_out_kernel<<<(T_TOKENS * HID / 4) / 256, 256>>>(out);

    dim3 g1(INTER / 128, NPAIRS / 128, NEXP);   // (16, 32, 8)
    gemm1_mma<<<g1, 256, g1_smem>>>(x, wi0, wi1);

    dim3 g2(HID / 128, NPAIRS / 128, NEXP);     // (8, 32, 8)
    gemm2_mma<<<g2, 256, g2_smem>>>(wo, out);
}